// round 1
// baseline (speedup 1.0000x reference)
#include <cuda_runtime.h>

#define BB 8
#define DD 256
#define NK 4096
#define TQ 1024

// ---------------------------------------------------------------------------
// GEMM1: S[b,n,t] = scale * sum_d K[b,d,n] * Q[b,d,t]
// K: (B, D, N) row-major over n; Q: (B, D, T) row-major over t.
// Block tile 64(n) x 64(t), k-tile 16 over d. 256 threads, 4x4 per thread.
// ---------------------------------------------------------------------------
__global__ void gemm_scores(const float* __restrict__ K,
                            const float* __restrict__ Q,
                            float* __restrict__ S) {
    __shared__ float Ks[16][64];
    __shared__ float Qs[16][64];

    const int b  = blockIdx.z;
    const int n0 = blockIdx.y * 64;
    const int t0 = blockIdx.x * 64;
    const int tid = threadIdx.x;
    const int tx = tid & 15;       // t micro index
    const int ty = tid >> 4;       // n micro index
    const int lk = tid >> 4;       // load: k row 0..15
    const int ls = (tid & 15) * 4; // load: col segment

    const float* Kb = K + (size_t)b * DD * NK;
    const float* Qb = Q + (size_t)b * DD * TQ;

    float c[4][4] = {};

    for (int k0 = 0; k0 < DD; k0 += 16) {
        float4 kv = *(const float4*)&Kb[(size_t)(k0 + lk) * NK + n0 + ls];
        float4 qv = *(const float4*)&Qb[(size_t)(k0 + lk) * TQ + t0 + ls];
        __syncthreads();
        *(float4*)&Ks[lk][ls] = kv;
        *(float4*)&Qs[lk][ls] = qv;
        __syncthreads();
#pragma unroll
        for (int kk = 0; kk < 16; kk++) {
            float av[4], bv[4];
            *(float4*)av = *(const float4*)&Ks[kk][ty * 4];
            *(float4*)bv = *(const float4*)&Qs[kk][tx * 4];
#pragma unroll
            for (int i = 0; i < 4; i++)
#pragma unroll
                for (int j = 0; j < 4; j++)
                    c[i][j] += av[i] * bv[j];
        }
    }

    const float scale = 0.0625f;  // 1/sqrt(256)
    float* Sb = S + (size_t)b * NK * TQ;
#pragma unroll
    for (int i = 0; i < 4; i++) {
        float4 o;
        o.x = c[i][0] * scale;
        o.y = c[i][1] * scale;
        o.z = c[i][2] * scale;
        o.w = c[i][3] * scale;
        *(float4*)&Sb[(size_t)(n0 + ty * 4 + i) * TQ + t0 + tx * 4] = o;
    }
}

// ---------------------------------------------------------------------------
// Softmax over n (axis=1) per (b,t) column, in place on A; argmax -> Mx.
// Block: (32 t-lanes, 16 n-partitions). Grid: (T/32, B).
// 3 strided-coalesced reads + 1 write of A.
// ---------------------------------------------------------------------------
__global__ void softmax_argmax(float* __restrict__ A, float* __restrict__ Mx) {
    const int b  = blockIdx.y;
    const int tx = threadIdx.x;          // 0..31
    const int ty = threadIdx.y;          // 0..15
    const int t  = blockIdx.x * 32 + tx;

    float* Ab = A + (size_t)b * NK * TQ + t;

    __shared__ float sm[16][33];
    __shared__ int   si[16][33];
    __shared__ float ss[16][33];

    // pass 1: max + argmax (first occurrence)
    float m = -3.0e38f;
    int idx = 0;
#pragma unroll 4
    for (int n = ty; n < NK; n += 16) {
        float s = Ab[(size_t)n * TQ];
        if (s > m) { m = s; idx = n; }
    }
    sm[ty][tx] = m;
    si[ty][tx] = idx;
    __syncthreads();
    if (ty == 0) {
#pragma unroll
        for (int r = 1; r < 16; r++) {
            float v = sm[r][tx];
            int   j = si[r][tx];
            if (v > m || (v == m && j < idx)) { m = v; idx = j; }
        }
        sm[0][tx] = m;
        Mx[(size_t)b * TQ + t] = (float)idx;
    }
    __syncthreads();
    m = sm[0][tx];

    // pass 2: sum of exp
    float sum = 0.0f;
#pragma unroll 4
    for (int n = ty; n < NK; n += 16)
        sum += __expf(Ab[(size_t)n * TQ] - m);
    ss[ty][tx] = sum;
    __syncthreads();
    if (ty == 0) {
#pragma unroll
        for (int r = 1; r < 16; r++) sum += ss[r][tx];
        ss[0][tx] = 1.0f / sum;
    }
    __syncthreads();
    const float inv = ss[0][tx];

    // pass 3: normalize in place
#pragma unroll 4
    for (int n = ty; n < NK; n += 16) {
        size_t o = (size_t)n * TQ;
        Ab[o] = __expf(Ab[o] - m) * inv;
    }
}

// ---------------------------------------------------------------------------
// GEMM2: R[b,m,t] = sum_n V[b,m,n] * A[b,n,t]   (m = head dim 0..255)
// Output goes to the R_ region: offset b*2D*T + m*T + t.
// Block tile 64(m) x 64(t), k-tile 16 over n.
// ---------------------------------------------------------------------------
__global__ void gemm_out(const float* __restrict__ V,
                         const float* __restrict__ A,
                         float* __restrict__ O) {
    __shared__ float Vs[16][68];  // padded: 16B-aligned rows, reduced STS conflicts
    __shared__ float As[16][64];

    const int b  = blockIdx.z;
    const int m0 = blockIdx.y * 64;
    const int t0 = blockIdx.x * 64;
    const int tid = threadIdx.x;
    const int tx = tid & 15;
    const int ty = tid >> 4;

    // V load map: each thread loads a float4 along n
    const int vm = tid >> 2;          // 0..63 (m within tile)
    const int vk = (tid & 3) * 4;     // k segment
    // A load map
    const int lk = tid >> 4;          // 0..15
    const int ls = (tid & 15) * 4;

    const float* Vb = V + (size_t)b * DD * NK;
    const float* Ab = A + (size_t)b * NK * TQ;

    float c[4][4] = {};

    for (int k0 = 0; k0 < NK; k0 += 16) {
        float4 vv = *(const float4*)&Vb[(size_t)(m0 + vm) * NK + k0 + vk];
        float4 av = *(const float4*)&Ab[(size_t)(k0 + lk) * TQ + t0 + ls];
        __syncthreads();
        Vs[vk + 0][vm] = vv.x;
        Vs[vk + 1][vm] = vv.y;
        Vs[vk + 2][vm] = vv.z;
        Vs[vk + 3][vm] = vv.w;
        *(float4*)&As[lk][ls] = av;
        __syncthreads();
#pragma unroll
        for (int kk = 0; kk < 16; kk++) {
            float mv[4], bv[4];
            *(float4*)mv = *(const float4*)&Vs[kk][ty * 4];
            *(float4*)bv = *(const float4*)&As[kk][tx * 4];
#pragma unroll
            for (int i = 0; i < 4; i++)
#pragma unroll
                for (int j = 0; j < 4; j++)
                    c[i][j] += mv[i] * bv[j];
        }
    }

    float* Ob = O + (size_t)b * (2 * DD) * TQ;
#pragma unroll
    for (int i = 0; i < 4; i++) {
        float4 o;
        o.x = c[i][0]; o.y = c[i][1]; o.z = c[i][2]; o.w = c[i][3];
        *(float4*)&Ob[(size_t)(m0 + ty * 4 + i) * TQ + t0 + tx * 4] = o;
    }
}

// ---------------------------------------------------------------------------
// Copy Q into the second half of R_ (concat along head dim).
// Per batch, Q's D*T block maps to a contiguous destination block.
// ---------------------------------------------------------------------------
__global__ void copy_q(const float* __restrict__ Q, float* __restrict__ O) {
    const size_t per   = (size_t)DD * TQ;       // 262144
    const size_t total = (size_t)BB * per;      // in floats
    size_t i = (size_t)blockIdx.x * blockDim.x + threadIdx.x;
    const size_t stride = (size_t)gridDim.x * blockDim.x;
    for (size_t e = i * 4; e < total; e += stride * 4) {
        size_t b = e / per;
        size_t r = e - b * per;
        float4 v = *(const float4*)&Q[e];
        *(float4*)&O[b * (size_t)(2 * DD) * TQ + per + r] = v;
    }
}

extern "C" void kernel_launch(void* const* d_in, const int* in_sizes, int n_in,
                              void* d_out, int out_size) {
    const float* K = (const float*)d_in[0];
    const float* V = (const float*)d_in[1];
    const float* Q = (const float*)d_in[2];
    float* out = (float*)d_out;

    float* R  = out;                                   // B*2D*T
    float* A  = out + (size_t)BB * 2 * DD * TQ;        // B*N*T
    float* MX = A + (size_t)BB * NK * TQ;              // B*T

    dim3 g1(TQ / 64, NK / 64, BB);
    gemm_scores<<<g1, 256>>>(K, Q, A);

    dim3 gs(TQ / 32, BB);
    softmax_argmax<<<gs, dim3(32, 16)>>>(A, MX);

    dim3 g2(TQ / 64, DD / 64, BB);
    gemm_out<<<g2, 256>>>(V, A, R);

    copy_q<<<512, 256>>>(Q, R);
}